// round 4
// baseline (speedup 1.0000x reference)
#include <cuda_runtime.h>

#define B_    4
#define NIN   512
#define NOUT  1024
#define C_    64
#define LOG2E 1.4426950408889634f

// Scratch (allocation-free rule: __device__ globals)
__device__ float g_yw[B_ * NIN];   // per-(b,n) channel-collapsed y·w
__device__ float g_kd[C_];         // per-channel exponent coefficient (log2 domain)
__device__ float g_wc[C_];         // w copy for fallback path
__device__ int   g_uniform;        // 1 if all sigma identical (bitwise)
__device__ float g_kd0;
__device__ float g_bias;

__device__ __forceinline__ float ex2f(float a) {
    float r;
    asm("ex2.approx.ftz.f32 %0, %1;" : "=f"(r) : "f"(a));
    return r;
}

// ---------------------------------------------------------------------------
// Prep: yw[b,n] = sum_c y[b,n,c] * w[c];  kd_c = -0.5*log2e*exp(-2*sigma_c)
// grid: 8 blocks x 256 threads (2048 threads == B_*NIN rows)
// ---------------------------------------------------------------------------
__global__ void prep_kernel(const float* __restrict__ y,
                            const float* __restrict__ sigma,
                            const float* __restrict__ w,
                            const float* __restrict__ bias) {
    int tid = blockIdx.x * blockDim.x + threadIdx.x;

    if (blockIdx.x == 0 && threadIdx.x < C_) {
        // scale = exp(sigma); 1/scale^2 = exp(-2 sigma)
        float sg = sigma[threadIdx.x];
        float s2inv = expf(-2.0f * sg);
        float kd = -0.5f * LOG2E * s2inv;            // exponent coeff in log2 domain
        g_kd[threadIdx.x] = kd;
        g_wc[threadIdx.x] = w[threadIdx.x];

        // warp-parallel uniformity check (channels 0..31 vs 32..63 + lane bcast)
        if (threadIdx.x < 32) {
            unsigned b0 = __float_as_uint(sigma[threadIdx.x]);
            unsigned b1 = __float_as_uint(sigma[threadIdx.x + 32]);
            unsigned ref = __shfl_sync(0xffffffffu, b0, 0);
            unsigned ok  = __ballot_sync(0xffffffffu, b0 == ref && b1 == ref);
            if (threadIdx.x == 0) {
                g_uniform = (ok == 0xffffffffu);
                g_kd0  = kd;
                g_bias = bias[0];
            }
        }
    }

    if (tid < B_ * NIN) {
        const float4* yrow = reinterpret_cast<const float4*>(y + (size_t)tid * C_);
        float acc = 0.0f;
        #pragma unroll
        for (int i = 0; i < C_ / 4; i++) {
            float4 yv = yrow[i];
            acc += yv.x * __ldg(&w[4*i + 0]);
            acc += yv.y * __ldg(&w[4*i + 1]);
            acc += yv.z * __ldg(&w[4*i + 2]);
            acc += yv.w * __ldg(&w[4*i + 3]);
        }
        g_yw[tid] = acc;
    }
}

// ---------------------------------------------------------------------------
// Main: one warp per output (b,m). 512 blocks x 256 threads = 4096 warps.
// Each block covers 8 consecutive outputs, all in the same batch b
// (1024 outputs per b, 1024 % 8 == 0), so x[b,:] / yw[b,:] staged in smem.
// ---------------------------------------------------------------------------
__global__ void __launch_bounds__(256)
main_kernel(const float* __restrict__ x,
            const float* __restrict__ t,
            const float* __restrict__ y,
            float* __restrict__ out) {
    __shared__ float sx[NIN];
    __shared__ float syw[NIN];

    const int warp = threadIdx.x >> 5;
    const int lane = threadIdx.x & 31;
    const int o0   = blockIdx.x * 8;      // first output of this block
    const int b    = o0 >> 10;            // NOUT = 1024

    for (int i = threadIdx.x; i < NIN; i += blockDim.x) {
        sx[i]  = x[b * NIN + i];
        syw[i] = g_yw[b * NIN + i];
    }
    __syncthreads();

    const int   o  = o0 + warp;
    const float tm = t[o];
    float acc = 0.0f;

    if (g_uniform) {
        const float kd = g_kd0;
        #pragma unroll
        for (int i = 0; i < NIN / 32; i++) {
            int   n = i * 32 + lane;
            float d = sx[n] - tm;
            acc += syw[n] * ex2f(kd * d * d);
        }
        #pragma unroll
        for (int off = 16; off; off >>= 1)
            acc += __shfl_xor_sync(0xffffffffu, acc, off);
        if (lane == 0) out[o] = acc + g_bias;
    } else {
        // General per-channel-scale fallback: lanes own 2 channels each.
        const int   c0 = lane, c1 = lane + 32;
        const float k0 = g_kd[c0], k1 = g_kd[c1];
        const float w0 = g_wc[c0], w1 = g_wc[c1];
        float a0 = 0.0f, a1 = 0.0f;
        for (int n = 0; n < NIN; n++) {
            float d  = sx[n] - tm;
            float d2 = d * d;
            const float* yr = y + ((size_t)(b * NIN + n)) * C_;
            a0 += __ldg(&yr[c0]) * ex2f(k0 * d2);
            a1 += __ldg(&yr[c1]) * ex2f(k1 * d2);
        }
        float acc2 = a0 * w0 + a1 * w1;
        #pragma unroll
        for (int off = 16; off; off >>= 1)
            acc2 += __shfl_xor_sync(0xffffffffu, acc2, off);
        if (lane == 0) out[o] = acc2 + g_bias;
    }
}

// ---------------------------------------------------------------------------
// Input order (setup_inputs): x, y, t, sigma, w, b
// ---------------------------------------------------------------------------
extern "C" void kernel_launch(void* const* d_in, const int* in_sizes, int n_in,
                              void* d_out, int out_size) {
    const float* x     = (const float*)d_in[0];
    const float* y     = (const float*)d_in[1];
    const float* t     = (const float*)d_in[2];
    const float* sigma = (const float*)d_in[3];
    const float* w     = (const float*)d_in[4];
    const float* bias  = (const float*)d_in[5];
    float* out = (float*)d_out;

    prep_kernel<<<(B_ * NIN + 255) / 256, 256>>>(y, sigma, w, bias);
    main_kernel<<<(B_ * NOUT) / 8, 256>>>(x, t, y, out);
}

// round 7
// speedup vs baseline: 1.6631x; 1.6631x over previous
#include <cuda_runtime.h>

#define B_    4
#define NIN   512
#define NOUT  1024
#define C_    64
#define LOG2E 1.4426950408889634f

// Scratch (allocation-free rule: __device__ globals)
__device__ float g_yw[B_ * NIN];   // per-(b,n) channel-collapsed y·w
__device__ float g_kd[C_];         // per-channel exponent coefficient (log2 domain)
__device__ float g_wc[C_];         // w copy for fallback path
__device__ int   g_uniform;        // 1 if all sigma identical (bitwise)
__device__ float g_kd0;
__device__ float g_bias;

__device__ __forceinline__ float ex2f(float a) {
    float r;
    asm("ex2.approx.ftz.f32 %0, %1;" : "=f"(r) : "f"(a));
    return r;
}

// ---------------------------------------------------------------------------
// Prep: yw[b,n] = sum_c y[b,n,c] * w[c]
// 64 blocks x 256 threads; 8 threads per row (2 float4 = 8 channels each),
// w staged in smem, sub-warp shfl reduce. Avoids the 8-block LSU-floor
// serialization of the original version (4096 LDG/block -> ~530 LDG/block).
// ---------------------------------------------------------------------------
__global__ void __launch_bounds__(256)
prep_kernel(const float* __restrict__ y,
            const float* __restrict__ sigma,
            const float* __restrict__ w,
            const float* __restrict__ bias) {
    __shared__ float4 sw[C_ / 4];          // 16 float4 = 64 floats

    if (threadIdx.x < C_ / 4)
        sw[threadIdx.x] = ((const float4*)w)[threadIdx.x];

    // sigma -> kd, uniformity flag (block 0 only)
    if (blockIdx.x == 0 && threadIdx.x < C_) {
        float sg = sigma[threadIdx.x];
        float kd = -0.5f * LOG2E * expf(-2.0f * sg);
        g_kd[threadIdx.x] = kd;
        g_wc[threadIdx.x] = w[threadIdx.x];
        if (threadIdx.x < 32) {
            unsigned b0 = __float_as_uint(sigma[threadIdx.x]);
            unsigned b1 = __float_as_uint(sigma[threadIdx.x + 32]);
            unsigned ref = __shfl_sync(0xffffffffu, b0, 0);
            unsigned ok  = __ballot_sync(0xffffffffu, b0 == ref && b1 == ref);
            if (threadIdx.x == 0) {
                g_uniform = (ok == 0xffffffffu);
                g_kd0  = kd;
                g_bias = bias[0];
            }
        }
    }
    __syncthreads();

    const int tid = blockIdx.x * 256 + threadIdx.x;   // 16384 threads total
    const int row = tid >> 3;                         // 0 .. B_*NIN-1
    const int sub = tid & 7;                          // 8-channel group

    const float4* yp = (const float4*)(y + (size_t)row * C_ + sub * 8);
    float4 y0 = yp[0];
    float4 y1 = yp[1];
    float4 w0 = sw[sub * 2 + 0];
    float4 w1 = sw[sub * 2 + 1];

    float acc = y0.x * w0.x + y0.y * w0.y + y0.z * w0.z + y0.w * w0.w
              + y1.x * w1.x + y1.y * w1.y + y1.z * w1.z + y1.w * w1.w;

    // reduce over the 8 threads of this row (width-8 sub-warp)
    acc += __shfl_down_sync(0xffffffffu, acc, 4, 8);
    acc += __shfl_down_sync(0xffffffffu, acc, 2, 8);
    acc += __shfl_down_sync(0xffffffffu, acc, 1, 8);
    if (sub == 0) g_yw[row] = acc;
}

// ---------------------------------------------------------------------------
// Main: 256 blocks x 256 threads. Block covers 16 consecutive outputs of one
// batch (NOUT=1024 -> 64 blocks per batch). Each warp owns 2 outputs.
// x / yw rows staged in smem (1 float4 per thread), then pulled into
// registers per lane (lane owns 16 contiguous n) -> zero LDS in inner loop,
// two interleaved EX2/FFMA chains for MUFU ILP.
// ---------------------------------------------------------------------------
__global__ void __launch_bounds__(256)
main_kernel(const float* __restrict__ x,
            const float* __restrict__ t,
            const float* __restrict__ y,
            float* __restrict__ out) {
    __shared__ float4 sx4[NIN / 4];        // 128 float4
    __shared__ float4 syw4[NIN / 4];       // 128 float4

    const int warp = threadIdx.x >> 5;
    const int lane = threadIdx.x & 31;
    const int o0   = blockIdx.x * 16;      // first output of this block
    const int b    = o0 >> 10;             // NOUT = 1024

    // staging: 256 float4 total, 1 per thread
    if (threadIdx.x < 128)
        sx4[threadIdx.x]        = ((const float4*)(x + b * NIN))[threadIdx.x];
    else
        syw4[threadIdx.x - 128] = ((const float4*)(g_yw + b * NIN))[threadIdx.x - 128];
    __syncthreads();

    const int   oA = o0 + warp * 2;
    const int   oB = oA + 1;
    const float tA = t[oA];
    const float tB = t[oB];

    if (g_uniform) {
        const float kd = g_kd0;
        float accA = 0.0f, accB = 0.0f;
        // lane owns n = lane*16 .. lane*16+15 (register-resident)
        #pragma unroll
        for (int q = 0; q < 4; q++) {
            float4 xv = sx4 [lane * 4 + q];
            float4 wv = syw4[lane * 4 + q];
            float d;
            d = xv.x - tA; accA += wv.x * ex2f(kd * d * d);
            d = xv.x - tB; accB += wv.x * ex2f(kd * d * d);
            d = xv.y - tA; accA += wv.y * ex2f(kd * d * d);
            d = xv.y - tB; accB += wv.y * ex2f(kd * d * d);
            d = xv.z - tA; accA += wv.z * ex2f(kd * d * d);
            d = xv.z - tB; accB += wv.z * ex2f(kd * d * d);
            d = xv.w - tA; accA += wv.w * ex2f(kd * d * d);
            d = xv.w - tB; accB += wv.w * ex2f(kd * d * d);
        }
        #pragma unroll
        for (int off = 16; off; off >>= 1) {
            accA += __shfl_xor_sync(0xffffffffu, accA, off);
            accB += __shfl_xor_sync(0xffffffffu, accB, off);
        }
        if (lane == 0) {
            out[oA] = accA + g_bias;
            out[oB] = accB + g_bias;
        }
    } else {
        // General per-channel-scale fallback: lanes own 2 channels each.
        const int   c0 = lane, c1 = lane + 32;
        const float k0 = g_kd[c0], k1 = g_kd[c1];
        const float w0 = g_wc[c0], w1 = g_wc[c1];
        const float* sx = (const float*)sx4;
        #pragma unroll
        for (int oo = 0; oo < 2; oo++) {
            const int   o  = oA + oo;
            const float tm = (oo == 0) ? tA : tB;
            float a0 = 0.0f, a1 = 0.0f;
            for (int n = 0; n < NIN; n++) {
                float d  = sx[n] - tm;
                float d2 = d * d;
                const float* yr = y + ((size_t)(b * NIN + n)) * C_;
                a0 += __ldg(&yr[c0]) * ex2f(k0 * d2);
                a1 += __ldg(&yr[c1]) * ex2f(k1 * d2);
            }
            float acc2 = a0 * w0 + a1 * w1;
            #pragma unroll
            for (int off = 16; off; off >>= 1)
                acc2 += __shfl_xor_sync(0xffffffffu, acc2, off);
            if (lane == 0) out[o] = acc2 + g_bias;
        }
    }
}

// ---------------------------------------------------------------------------
// Input order (setup_inputs): x, y, t, sigma, w, b
// ---------------------------------------------------------------------------
extern "C" void kernel_launch(void* const* d_in, const int* in_sizes, int n_in,
                              void* d_out, int out_size) {
    const float* x     = (const float*)d_in[0];
    const float* y     = (const float*)d_in[1];
    const float* t     = (const float*)d_in[2];
    const float* sigma = (const float*)d_in[3];
    const float* w     = (const float*)d_in[4];
    const float* bias  = (const float*)d_in[5];
    float* out = (float*)d_out;

    prep_kernel<<<(B_ * NIN * 8) / 256, 256>>>(y, sigma, w, bias);
    main_kernel<<<(B_ * NOUT) / 16, 256>>>(x, t, y, out);
}